// round 15
// baseline (speedup 1.0000x reference)
#include <cuda_runtime.h>
#include <cstdint>

// Problem constants (fixed by the reference)
#define BB    2
#define SEQ   2048
#define HID   2048
#define NHEAD 16
#define DHEAD 128
#define MTOT  (BB * SEQ)      // 4096
#define NQKV  (3 * HID)       // 6144
#define QSCALE 0.088388347648318447f

// ---------------------------------------------------------------------------
// Device scratch (all 16B-aligned for cp.async / vector access)
// ---------------------------------------------------------------------------
__device__ __align__(128) uint16_t g_qh[(size_t)BB * NHEAD * SEQ * DHEAD];  // fp16
__device__ __align__(128) uint16_t g_kh[(size_t)BB * NHEAD * SEQ * DHEAD];  // fp16
__device__ __align__(128) uint16_t g_vh[(size_t)BB * NHEAD * SEQ * DHEAD];  // fp16

__device__ __align__(128) uint16_t g_hidh[(size_t)MTOT * HID];   // fp16 rounded
__device__ __align__(128) uint16_t g_wah[(size_t)HID * NQKV];    // fp16 rounded
__device__ __align__(128) uint16_t g_wph[(size_t)HID * HID];     // fp16 rounded
__device__ __align__(128) uint16_t g_ath[(size_t)MTOT * HID];    // fp16 rounded attn

// ---------------------------------------------------------------------------
// Helpers
// ---------------------------------------------------------------------------
__device__ __forceinline__ uint32_t round_pack_h(float x0, float x1) {
    uint32_t h;
    asm("cvt.rn.f16x2.f32 %0, %1, %2;" : "=r"(h) : "f"(x1), "f"(x0));
    return h;
}

__device__ __forceinline__ uint32_t smem_u32(const void *p) {
    uint32_t a;
    asm("{ .reg .u64 t; cvta.to.shared.u64 t, %1; cvt.u32.u64 %0, t; }"
        : "=r"(a) : "l"(p));
    return a;
}

// fp16 mma, fp32 accumulate
__device__ __forceinline__ void mma16h(float *d,
                                       uint32_t a0, uint32_t a1, uint32_t a2, uint32_t a3,
                                       uint32_t b0, uint32_t b1) {
    asm volatile(
        "mma.sync.aligned.m16n8k16.row.col.f32.f16.f16.f32 "
        "{%0,%1,%2,%3}, {%4,%5,%6,%7}, {%8,%9}, {%0,%1,%2,%3};\n"
        : "+f"(d[0]), "+f"(d[1]), "+f"(d[2]), "+f"(d[3])
        : "r"(a0), "r"(a1), "r"(a2), "r"(a3), "r"(b0), "r"(b1));
}

#define LDSM4(r, addr)                                                       \
    asm volatile("ldmatrix.sync.aligned.m8n8.x4.shared.b16 {%0,%1,%2,%3}, [%4];" \
        : "=r"((r)[0]), "=r"((r)[1]), "=r"((r)[2]), "=r"((r)[3]) : "r"(addr))
#define LDSM4T(r, addr)                                                      \
    asm volatile("ldmatrix.sync.aligned.m8n8.x4.trans.shared.b16 {%0,%1,%2,%3}, [%4];" \
        : "=r"((r)[0]), "=r"((r)[1]), "=r"((r)[2]), "=r"((r)[3]) : "r"(addr))

__device__ __forceinline__ void cpa16(uint32_t dst, const void *src) {
    asm volatile("cp.async.cg.shared.global [%0], [%1], 16;"
                 :: "r"(dst), "l"(src) : "memory");
}
#define CP_COMMIT() asm volatile("cp.async.commit_group;" ::: "memory")
#define CP_WAIT2()  asm volatile("cp.async.wait_group 2;" ::: "memory")
#define CP_WAIT0()  asm volatile("cp.async.wait_group 0;" ::: "memory")

// ---------------------------------------------------------------------------
// Round kernel: fp32 -> fp16 (row-major preserved)
// ---------------------------------------------------------------------------
__global__ void __launch_bounds__(256)
round4h(const float4 *__restrict__ x, uint2 *__restrict__ hi) {
    int i = blockIdx.x * 256 + threadIdx.x;
    float4 v = x[i];
    hi[i] = make_uint2(round_pack_h(v.x, v.y), round_pack_h(v.z, v.w));
}

// ---------------------------------------------------------------------------
// GEMM: C = A @ B + bias, fp16 inputs, single pass, fp32 accumulate.
// CTA tile 128m x 256n, 256 threads = 8 warps (2 wm x 4 wn), warp tile 64x64
// (MMA:LDSM ratio 4:1 -> higher tensor-issue ceiling than 64x32).
// 4-stage cp.async; stage = A 10240 | B 16384 = 26624 B.
// MODE 1: QKV epilogue scatters fp16 Q (pre-scaled), K, V | MODE 0: fp32 out.
// ---------------------------------------------------------------------------
#define STG_BYTES 26624
#define OFF_A 0
#define OFF_B 10240
#define GEMM_SMEM (4 * STG_BYTES)

template <int MODE>
__global__ void __launch_bounds__(256)
gemm_ldsm(const uint16_t *__restrict__ Ah, const uint16_t *__restrict__ Bh,
          const float *__restrict__ bias, float *__restrict__ Cout,
          int M, int N, int K) {
    extern __shared__ char smc[];
    const uint32_t sbase = smem_u32(smc);

    const int tid  = threadIdx.x;
    const int lane = tid & 31;
    const int warp = tid >> 5;
    const int wm   = warp >> 2;      // 0..1
    const int wn   = warp & 3;       // 0..3
    const int m0   = blockIdx.y * 128;
    const int n0   = blockIdx.x * 256;
    const int g    = lane >> 2;
    const int q4   = lane & 3;

    float acc[4][8][4];
#pragma unroll
    for (int i = 0; i < 4; i++)
#pragma unroll
        for (int j = 0; j < 8; j++)
#pragma unroll
            for (int e = 0; e < 4; e++) acc[i][j][e] = 0.f;

    auto issue = [&](int s) {
        const uint32_t sb = sbase + (s & 3) * STG_BYTES;
        const int kb = s << 5;
        // A: 128 rows x 4 chunks = 512 ids, 2 iters
#pragma unroll
        for (int i = 0; i < 2; i++) {
            int id  = tid + i * 256;
            int row = id >> 2;
            int c   = id & 3;
            cpa16(sb + OFF_A + ((row * 5 + c) << 4),
                  Ah + (size_t)(m0 + row) * K + kb + c * 8);
        }
        // B: 32 k x 32 chunks = 1024 ids, 4 iters
#pragma unroll
        for (int i = 0; i < 4; i++) {
            int id = tid + i * 256;
            int k  = id >> 5;
            int c  = id & 31;
            cpa16(sb + OFF_B + (((k << 5) + (c ^ (k & 7))) << 4),
                  Bh + (size_t)(kb + k) * N + n0 + c * 8);
        }
    };

    auto compute = [&](int s) {
        const uint32_t sb = sbase + (s & 3) * STG_BYTES;
        const int arow = wm * 64 + (lane & 15);
        const int lt16 = lane >> 4;
        const int cbas = wn * 8 + ((lane >> 3) & 1);
#pragma unroll
        for (int kk = 0; kk < 2; kk++) {
            const int ac   = kk * 2 + lt16;
            const int kloc = kk * 16 + (lt16 << 3) + (lane & 7);

            uint32_t ah[4][4], bh[4][4];
#pragma unroll
            for (int mt = 0; mt < 4; mt++)
                LDSM4(ah[mt], sb + OFF_A + (((arow + mt * 16) * 5 + ac) << 4));
#pragma unroll
            for (int bt = 0; bt < 4; bt++) {
                int c = cbas + bt * 2;
                LDSM4T(bh[bt], sb + OFF_B + (((kloc << 5) + (c ^ (kloc & 7))) << 4));
            }

            // 32 MMAs per kk (8 per LDSM fragment set)
#pragma unroll
            for (int bt = 0; bt < 4; bt++)
#pragma unroll
                for (int mt = 0; mt < 4; mt++) {
                    mma16h(acc[mt][2 * bt],     ah[mt][0], ah[mt][1], ah[mt][2], ah[mt][3],
                           bh[bt][0], bh[bt][2]);
                    mma16h(acc[mt][2 * bt + 1], ah[mt][0], ah[mt][1], ah[mt][2], ah[mt][3],
                           bh[bt][1], bh[bt][3]);
                }
        }
    };

    const int S = K >> 5;
    issue(0); CP_COMMIT();
    issue(1); CP_COMMIT();
    issue(2); CP_COMMIT();

    for (int s = 0; s < S; s++) {
        CP_WAIT2();
        __syncthreads();
        compute(s);
        if (s + 3 < S) issue(s + 3);
        CP_COMMIT();
    }

    // ---- epilogue ----
#pragma unroll
    for (int mt = 0; mt < 4; mt++) {
#pragma unroll
        for (int nt = 0; nt < 8; nt++) {
            float c0 = acc[mt][nt][0];
            float c1 = acc[mt][nt][1];
            float c2 = acc[mt][nt][2];
            float c3 = acc[mt][nt][3];

            int row = m0 + wm * 64 + mt * 16 + g;
            int col = n0 + wn * 64 + nt * 8 + (q4 << 1);
            float b0 = bias[col];
            float b1 = bias[col + 1];
            if (MODE == 1) {
                int which = col >> 11;
                int head  = (col >> 7) & 15;
                int dc    = col & 127;
                int bi = row >> 11;
                int si = row & 2047;
                size_t u32i = (((size_t)(bi * NHEAD + head) * SEQ + si) * DHEAD + dc) >> 1;
                uint16_t *dh = (which == 0) ? g_qh : ((which == 1) ? g_kh : g_vh);
                float sc = (which == 0) ? QSCALE : 1.f;
                ((uint32_t *)dh)[u32i] =
                    round_pack_h((c0 + b0) * sc, (c1 + b1) * sc);
                ((uint32_t *)dh)[u32i + 8 * 64] =
                    round_pack_h((c2 + b0) * sc, (c3 + b1) * sc);
            } else {
                float2 v0 = make_float2(c0 + b0, c1 + b1);
                float2 v1 = make_float2(c2 + b0, c3 + b1);
                *(float2 *)(Cout + (size_t)row * N + col) = v0;
                *(float2 *)(Cout + (size_t)(row + 8) * N + col) = v1;
            }
        }
    }
}

// ---------------------------------------------------------------------------
// Flash attention (causal), single-pass fp16 (Q, K, V, P all fp16-rounded;
// accumulation in fp32). CTA: 128 Q rows, 8 warps x 16 rows. KV tile 64.
// smem u32: Q[128*68] | stage st: K[64*68] V[64*68]  -> 102 KB (2 CTAs/SM).
// Output: single fp16 attn (g_ath) for the single-pass proj GEMM.
// ---------------------------------------------------------------------------
#define FL_QU   (128 * 68)          // u32 for Q
#define FL_AU   (64 * 68)           // u32 per K/V array (4352)
#define FL_STGU (2 * FL_AU)         // 8704 u32 per stage
#define FLASH_SMEM ((FL_QU + 2 * FL_STGU) * 4)

__global__ void __launch_bounds__(256) flash_causal() {
    extern __shared__ uint32_t smf[];
    const uint32_t sbase = smem_u32(smf);

    const int qt   = (gridDim.x - 1) - blockIdx.x;   // heavy tiles first
    const int h    = blockIdx.y;
    const int b    = blockIdx.z;
    const int tid  = threadIdx.x;
    const int lane = tid & 31;
    const int warp = tid >> 5;
    const int g    = lane >> 2;
    const int q4   = lane & 3;

    const size_t headoff = (size_t)(b * NHEAD + h) * SEQ * DHEAD;
    const uint16_t *Qhg = g_qh + headoff;
    const uint16_t *Khg = g_kh + headoff;
    const uint16_t *Vhg = g_vh + headoff;

    const int qr0 = qt * 128;

    // ---- Q tile: 128 rows x 16 chunks = 2048 cp.async chunks ----
#pragma unroll
    for (int i = 0; i < 8; i++) {
        int id  = tid + i * 256;       // 0..2047
        int row = id >> 4;             // 0..127
        int c   = id & 15;
        cpa16(sbase + ((row * 68 + c * 4) << 2),
              Qhg + (size_t)(qr0 + row) * DHEAD + c * 8);
    }

    auto copy_kv = [&](int kv0, int st) {
        const uint32_t stb = sbase + ((FL_QU + st * FL_STGU) << 2);
#pragma unroll
        for (int i = 0; i < 8; i++) {
            int id  = tid + i * 256;                 // 0..2047
            int arr = id >> 10;                      // 0 = K, 1 = V
            int rc  = id & 1023;
            int row = rc >> 4;
            int c   = rc & 15;
            const uint16_t *base = (arr == 0) ? Khg : Vhg;
            cpa16(stb + ((arr * FL_AU + row * 68 + c * 4) << 2),
                  base + (size_t)(kv0 + row) * DHEAD + c * 8);
        }
    };

    float Oacc[16][4];
#pragma unroll
    for (int i = 0; i < 16; i++)
#pragma unroll
        for (int e = 0; e < 4; e++) Oacc[i][e] = 0.f;
    float m_i[2] = {-1e30f, -1e30f};
    float l_i[2] = {0.f, 0.f};

    const int wr0   = warp * 16;
    const int grow0 = qr0 + wr0;
    const int jmax  = 2 * qt + 1;

    copy_kv(0, 0);
    CP_COMMIT();

    const int lt = lane >> 3;      // tile index within x4 (0..3)
    const int lr = lane & 7;       // row within tile

    for (int j = 0; j <= jmax; j++) {
        const int kv0 = j * 64;
        CP_WAIT0();
        __syncthreads();
        if (j + 1 <= jmax) {
            copy_kv((j + 1) * 64, (j + 1) & 1);
            CP_COMMIT();
        }

        if (kv0 <= grow0 + 15) {
            const uint32_t QH = sbase;
            const uint32_t KH = sbase + ((FL_QU + (j & 1) * FL_STGU) << 2);
            const uint32_t VH = KH + (FL_AU << 2);

            // ---- S = Q @ K^T : 16 x 64 per warp (single pass) ----
            float sacc[8][4];
#pragma unroll
            for (int nt = 0; nt < 8; nt++)
#pragma unroll
                for (int e = 0; e < 4; e++) sacc[nt][e] = 0.f;

#pragma unroll
            for (int kk = 0; kk < 8; kk++) {
                uint32_t ah[4], bh[4][4];
                uint32_t qrow = wr0 + ((lt & 1) << 3) + lr;
                uint32_t qc   = (kk << 1) + (lt >> 1);
                LDSM4(ah, QH + ((qrow * 68 + qc * 4) << 2));
#pragma unroll
                for (int i = 0; i < 4; i++) {
                    uint32_t krow = (i << 4) + ((lt >> 1) << 3) + lr;
                    uint32_t kc   = (kk << 1) + (lt & 1);
                    LDSM4(bh[i], KH + ((krow * 68 + kc * 4) << 2));
                }
#pragma unroll
                for (int i = 0; i < 4; i++) {
                    mma16h(sacc[2 * i],     ah[0], ah[1], ah[2], ah[3], bh[i][0], bh[i][1]);
                    mma16h(sacc[2 * i + 1], ah[0], ah[1], ah[2], ah[3], bh[i][2], bh[i][3]);
                }
            }

            // ---- causal mask (near diagonal only) ----
            if (kv0 + 63 > grow0) {
                const int r0 = grow0 + g;
#pragma unroll
                for (int nt = 0; nt < 8; nt++) {
                    int c0 = kv0 + nt * 8 + (q4 << 1);
                    if (c0 > r0)         sacc[nt][0] = -1e30f;
                    if (c0 + 1 > r0)     sacc[nt][1] = -1e30f;
                    if (c0 > r0 + 8)     sacc[nt][2] = -1e30f;
                    if (c0 + 1 > r0 + 8) sacc[nt][3] = -1e30f;
                }
            }

            // ---- streaming softmax ----
            float rmax0 = -1e30f, rmax1 = -1e30f;
#pragma unroll
            for (int nt = 0; nt < 8; nt++) {
                rmax0 = fmaxf(rmax0, fmaxf(sacc[nt][0], sacc[nt][1]));
                rmax1 = fmaxf(rmax1, fmaxf(sacc[nt][2], sacc[nt][3]));
            }
            rmax0 = fmaxf(rmax0, __shfl_xor_sync(0xffffffffu, rmax0, 1));
            rmax0 = fmaxf(rmax0, __shfl_xor_sync(0xffffffffu, rmax0, 2));
            rmax1 = fmaxf(rmax1, __shfl_xor_sync(0xffffffffu, rmax1, 1));
            rmax1 = fmaxf(rmax1, __shfl_xor_sync(0xffffffffu, rmax1, 2));

            float mn0 = fmaxf(m_i[0], rmax0);
            float mn1 = fmaxf(m_i[1], rmax1);
            float alpha0 = __expf(m_i[0] - mn0);
            float alpha1 = __expf(m_i[1] - mn1);

            float rs0 = 0.f, rs1 = 0.f;
#pragma unroll
            for (int nt = 0; nt < 8; nt++) {
                sacc[nt][0] = __expf(sacc[nt][0] - mn0);
                sacc[nt][1] = __expf(sacc[nt][1] - mn0);
                sacc[nt][2] = __expf(sacc[nt][2] - mn1);
                sacc[nt][3] = __expf(sacc[nt][3] - mn1);
                rs0 += sacc[nt][0] + sacc[nt][1];
                rs1 += sacc[nt][2] + sacc[nt][3];
            }
            rs0 += __shfl_xor_sync(0xffffffffu, rs0, 1);
            rs0 += __shfl_xor_sync(0xffffffffu, rs0, 2);
            rs1 += __shfl_xor_sync(0xffffffffu, rs1, 1);
            rs1 += __shfl_xor_sync(0xffffffffu, rs1, 2);

            l_i[0] = l_i[0] * alpha0 + rs0;
            l_i[1] = l_i[1] * alpha1 + rs1;
            m_i[0] = mn0;
            m_i[1] = mn1;

#pragma unroll
            for (int nt = 0; nt < 16; nt++) {
                Oacc[nt][0] *= alpha0; Oacc[nt][1] *= alpha0;
                Oacc[nt][2] *= alpha1; Oacc[nt][3] *= alpha1;
            }

            // ---- O += P @ V (P fp16-rounded in regs; single pass) ----
#pragma unroll
            for (int c = 0; c < 4; c++) {
                uint32_t ph[4];
                ph[0] = round_pack_h(sacc[2 * c][0],     sacc[2 * c][1]);
                ph[1] = round_pack_h(sacc[2 * c][2],     sacc[2 * c][3]);
                ph[2] = round_pack_h(sacc[2 * c + 1][0], sacc[2 * c + 1][1]);
                ph[3] = round_pack_h(sacc[2 * c + 1][2], sacc[2 * c + 1][3]);
                const uint32_t srow = (c << 4) + ((lt & 1) << 3) + lr;
#pragma unroll
                for (int i = 0; i < 8; i++) {
                    uint32_t dc = (i << 1) + (lt >> 1);
                    uint32_t vh[4];
                    LDSM4T(vh, VH + ((srow * 68 + dc * 4) << 2));
                    mma16h(Oacc[2 * i],     ph[0], ph[1], ph[2], ph[3], vh[0], vh[1]);
                    mma16h(Oacc[2 * i + 1], ph[0], ph[1], ph[2], ph[3], vh[2], vh[3]);
                }
            }
        }
        __syncthreads();
    }

    // ---- epilogue: normalize, round fp16, write attn ----
    const float inv0 = 1.f / l_i[0];
    const float inv1 = 1.f / l_i[1];
    const int   s0   = qr0 + wr0 + g;
    const size_t base0 = ((size_t)(b * SEQ) + s0) * (HID / 2) + h * 64;
#pragma unroll
    for (int nt = 0; nt < 16; nt++) {
        uint32_t h0 = round_pack_h(Oacc[nt][0] * inv0, Oacc[nt][1] * inv0);
        uint32_t h1 = round_pack_h(Oacc[nt][2] * inv1, Oacc[nt][3] * inv1);
        size_t ci = base0 + nt * 4 + q4;
        ((uint32_t *)g_ath)[ci] = h0;
        ((uint32_t *)g_ath)[ci + 8 * (HID / 2)] = h1;
    }
}

// ---------------------------------------------------------------------------
// kernel_launch
// ---------------------------------------------------------------------------
extern "C" void kernel_launch(void *const *d_in, const int *in_sizes, int n_in,
                              void *d_out, int out_size) {
    (void)in_sizes; (void)n_in; (void)out_size;
    const float *hs     = (const float *)d_in[0];
    const float *w_attn = (const float *)d_in[1];
    const float *b_attn = (const float *)d_in[2];
    const float *w_proj = (const float *)d_in[3];
    const float *b_proj = (const float *)d_in[4];
    float *out = (float *)d_out;

    cudaFuncSetAttribute(gemm_ldsm<1>,
                         cudaFuncAttributeMaxDynamicSharedMemorySize, GEMM_SMEM);
    cudaFuncSetAttribute(gemm_ldsm<0>,
                         cudaFuncAttributeMaxDynamicSharedMemorySize, GEMM_SMEM);
    cudaFuncSetAttribute(flash_causal,
                         cudaFuncAttributeMaxDynamicSharedMemorySize, FLASH_SMEM);

    uint16_t *hidh, *wah, *wph, *ath;
    cudaGetSymbolAddress((void **)&hidh, g_hidh);
    cudaGetSymbolAddress((void **)&wah,  g_wah);
    cudaGetSymbolAddress((void **)&wph,  g_wph);
    cudaGetSymbolAddress((void **)&ath,  g_ath);

    // 0) pre-convert inputs: all fp16 rounded
    round4h<<<(MTOT * HID) / 1024, 256>>>((const float4 *)hs, (uint2 *)hidh);
    round4h<<<(HID * NQKV) / 1024, 256>>>((const float4 *)w_attn, (uint2 *)wah);
    round4h<<<(HID * HID) / 1024, 256>>>((const float4 *)w_proj, (uint2 *)wph);

    // 1) QKV projection -> fp16 Q (pre-scaled), K, V (single-pass)
    gemm_ldsm<1><<<dim3(NQKV / 256, MTOT / 128), 256, GEMM_SMEM>>>(
        hidh, wah, b_attn, nullptr, MTOT, NQKV, HID);

    // 2) causal flash attention -> fp16 attn (g_ath)
    flash_causal<<<dim3(SEQ / 128, NHEAD, BB), 256, FLASH_SMEM>>>();

    // 3) output projection -> d_out (single-pass)
    gemm_ldsm<0><<<dim3(HID / 256, MTOT / 128), 256, GEMM_SMEM>>>(
        ath, wph, b_proj, out, MTOT, HID, HID);
}